// round 4
// baseline (speedup 1.0000x reference)
#include <cuda_runtime.h>
#include <math.h>

#define BB 2
#define SS 2048
#define DD 1024
#define NH 16
#define NKV 4
#define QKB 16
#define VB 32
#define NREP (NH / NKV)
#define MROWS (BB * SS)   // 4096

typedef unsigned long long u64;

// ---- packed f32x2 helpers (sm_100+ packed-fp32 pipe: 2x FLOP per issue) ----
__device__ __forceinline__ u64 pack2(float lo, float hi) {
    u64 r; asm("mov.b64 %0, {%1, %2};" : "=l"(r) : "f"(lo), "f"(hi)); return r;
}
__device__ __forceinline__ void fma2(u64& d, u64 a, u64 b) {
    asm("fma.rn.f32x2 %0, %1, %2, %3;" : "=l"(d) : "l"(a), "l"(b), "l"(d));
}
__device__ __forceinline__ float2 unpack2(u64 v) {
    float2 f; asm("mov.b64 {%0, %1}, %2;" : "=f"(f.x), "=f"(f.y) : "l"(v)); return f;
}

// Scratch (allocation-free rule: __device__ globals)
__device__ float g_pq[BB * NH * SS * QKB];    // [b,h,s,16]   4 MB
__device__ float g_pk[BB * NKV * SS * QKB];   // [b,kv,s,16]  1 MB
__device__ float g_pv[BB * NKV * SS * VB];    // [b,kv,s,32]  2 MB
__device__ float g_ovh[BB * SS * NH * VB];    // [b,s,h*32]   8 MB

// ---------------------------------------------------------------------------
// SGEMM: C[M,N] = A[M,K] @ W[K,N], row-major. 64x64 tile, Ktile 16,
// 256 threads, 4x4 per thread, inner product on the packed f32x2 pipe.
// MODE 0: plain store.  MODE 1: sigmoid + scatter to [b, head, s, dd].
// ---------------------------------------------------------------------------
template <int MODE>
__global__ void __launch_bounds__(256) sgemm_kernel(
    const float* __restrict__ A, const float* __restrict__ W,
    float* __restrict__ C, int M, int N, int K, int dd)
{
    __shared__ float As[16][64];   // As[k][m]
    __shared__ float Bs[16][64];   // Bs[k][n]

    const int tid = threadIdx.x;
    const int tx = tid & 15;        // n
    const int ty = tid >> 4;        // m
    const int row0 = blockIdx.y * 64;
    const int col0 = blockIdx.x * 64;

    const int arow = tid >> 2;
    const int acol = (tid & 3) * 4;
    const int brow = tid >> 4;
    const int bcol = (tid & 15) * 4;

    const float* Aptr = A + (size_t)(row0 + arow) * K + acol;
    const float* Wptr = W + (size_t)brow * N + col0 + bcol;

    u64 acc2[4][2];
    const u64 z = pack2(0.f, 0.f);
#pragma unroll
    for (int i = 0; i < 4; i++) { acc2[i][0] = z; acc2[i][1] = z; }

    for (int kk = 0; kk < K; kk += 16) {
        float4 av = *(const float4*)Aptr;  Aptr += 16;
        float4 bv = *(const float4*)Wptr;  Wptr += (size_t)16 * N;

        As[acol + 0][arow] = av.x;
        As[acol + 1][arow] = av.y;
        As[acol + 2][arow] = av.z;
        As[acol + 3][arow] = av.w;
        *(float4*)&Bs[brow][bcol] = bv;
        __syncthreads();

#pragma unroll
        for (int k = 0; k < 16; k++) {
            float4 a4 = *(const float4*)&As[k][ty * 4];
            ulonglong2 bb = *(const ulonglong2*)&Bs[k][tx * 4];  // 4 floats as 2x f32x2
            float am[4] = {a4.x, a4.y, a4.z, a4.w};
#pragma unroll
            for (int i = 0; i < 4; i++) {
                u64 ai = pack2(am[i], am[i]);
                fma2(acc2[i][0], ai, bb.x);
                fma2(acc2[i][1], ai, bb.y);
            }
        }
        __syncthreads();
    }

    if (MODE == 0) {
#pragma unroll
        for (int i = 0; i < 4; i++) {
            int m = row0 + ty * 4 + i;
            float2 c0 = unpack2(acc2[i][0]);
            float2 c1 = unpack2(acc2[i][1]);
            float4 st = make_float4(c0.x, c0.y, c1.x, c1.y);
            *(float4*)&C[(size_t)m * N + col0 + tx * 4] = st;
        }
    } else {
        const int nheads = N / dd;
#pragma unroll
        for (int i = 0; i < 4; i++) {
            int m = row0 + ty * 4 + i;
            int b = m / SS;
            int s = m - b * SS;
            float2 c0 = unpack2(acc2[i][0]);
            float2 c1 = unpack2(acc2[i][1]);
            float cv[4] = {c0.x, c0.y, c1.x, c1.y};
#pragma unroll
            for (int j = 0; j < 4; j++) {
                int n = col0 + tx * 4 + j;
                int head = n / dd;
                int d = n - head * dd;
                float v = 1.f / (1.f + __expf(-cv[j]));
                C[(((size_t)(b * nheads + head) * SS) + s) * dd + d] = v;
            }
        }
    }
}

// ---------------------------------------------------------------------------
// Streaming causal attention, f32x2 math path.
// 128 threads/CTA, 1 thread = 1 query, 128-key smem tiles.
// score = (QKB - sum(pq)) + sum_d (2*pq_d - 1)*pk_d, score in [0,16]:
// no softmax max-subtraction needed in fp32.
// ---------------------------------------------------------------------------
#define ATT_BM 128
#define ATT_BN 128

__global__ void __launch_bounds__(ATT_BM) rosa_attn_kernel(
    const float* __restrict__ pq, const float* __restrict__ pk,
    const float* __restrict__ pv, const float* __restrict__ e0,
    const float* __restrict__ e1, float* __restrict__ ovh)
{
    const int sblk = blockIdx.x;
    const int h    = blockIdx.y;
    const int b    = blockIdx.z;
    const int kvh  = h / NREP;
    const int tid  = threadIdx.x;
    const int s    = sblk * ATT_BM + tid;

    __shared__ float sk[ATT_BN][QKB];   // 8 KB, row = 64B (16B aligned)
    __shared__ float sv[ATT_BN][VB];    // 16 KB, row = 128B

    // Query transform: qm = 2*pq - 1 (packed), c = QKB - sum(pq)
    const float* qrow = pq + (((size_t)(b * NH + h) * SS) + s) * QKB;
    u64 qm2[QKB / 2];
    float c = (float)QKB;
#pragma unroll
    for (int i = 0; i < QKB / 2; i++) {
        float x0 = qrow[2 * i], x1 = qrow[2 * i + 1];
        c -= x0 + x1;
        qm2[i] = pack2(2.f * x0 - 1.f, 2.f * x1 - 1.f);
    }

    u64 num2[VB / 2];
    const u64 z = pack2(0.f, 0.f);
#pragma unroll
    for (int i = 0; i < VB / 2; i++) num2[i] = z;
    float den = 0.f;

    const float* pk_base = pk + ((size_t)(b * NKV + kvh) * SS) * QKB;
    const float* pv_base = pv + ((size_t)(b * NKV + kvh) * SS) * VB;

    const int ntiles = sblk + 1;
    for (int t = 0; t < ntiles; t++) {
        const int t0 = t * ATT_BN;
        __syncthreads();
        {   // coalesced contiguous tile loads
            const float4* kt = (const float4*)(pk_base + (size_t)t0 * QKB);
            float4* skf = (float4*)&sk[0][0];
#pragma unroll
            for (int i = 0; i < (ATT_BN * QKB / 4) / ATT_BM; i++)
                skf[i * ATT_BM + tid] = kt[i * ATT_BM + tid];
            const float4* vt = (const float4*)(pv_base + (size_t)t0 * VB);
            float4* svf = (float4*)&sv[0][0];
#pragma unroll
            for (int i = 0; i < (ATT_BN * VB / 4) / ATT_BM; i++)
                svf[i * ATT_BM + tid] = vt[i * ATT_BM + tid];
        }
        __syncthreads();

        const int jmax = (t == ntiles - 1) ? (tid + 1) : ATT_BN;
#pragma unroll 2
        for (int j = 0; j < jmax; j++) {
            // dot on packed pipe: 4x LDS.128 + 8x FFMA2
            const ulonglong2* skr = (const ulonglong2*)&sk[j][0];
            u64 acc2 = z;
#pragma unroll
            for (int i = 0; i < 4; i++) {
                ulonglong2 kk = skr[i];
                fma2(acc2, qm2[2 * i],     kk.x);
                fma2(acc2, qm2[2 * i + 1], kk.y);
            }
            float2 ds = unpack2(acc2);
            float p = __expf(c + ds.x + ds.y);   // TAU=1, score in [0,16]
            den += p;
            u64 p2 = pack2(p, p);
            // accumulate: 8x LDS.128 + 16x FFMA2
            const ulonglong2* svr = (const ulonglong2*)&sv[j][0];
#pragma unroll
            for (int i = 0; i < 8; i++) {
                ulonglong2 vv = svr[i];
                fma2(num2[2 * i],     p2, vv.x);
                fma2(num2[2 * i + 1], p2, vv.y);
            }
        }
    }

    const float inv = 1.f / den;
    float* orow = ovh + (((size_t)(b * SS + s) * NH) + h) * VB;
#pragma unroll
    for (int i = 0; i < VB / 2; i++) {
        float2 f = unpack2(num2[i]);
        int d0 = 2 * i, d1 = 2 * i + 1;
        float a00 = e0[h * VB + d0], a10 = e1[h * VB + d0];
        float a01 = e0[h * VB + d1], a11 = e1[h * VB + d1];
        orow[d0] = fmaf(a10 - a00, f.x * inv, a00);
        orow[d1] = fmaf(a11 - a01, f.y * inv, a01);
    }
}

// ---------------------------------------------------------------------------
extern "C" void kernel_launch(void* const* d_in, const int* in_sizes, int n_in,
                              void* d_out, int out_size)
{
    const float* hs = (const float*)d_in[0];
    const float* Wq = (const float*)d_in[1];
    const float* Wk = (const float*)d_in[2];
    const float* Wv = (const float*)d_in[3];
    const float* Wo = (const float*)d_in[4];
    const float* e0 = (const float*)d_in[5];
    const float* e1 = (const float*)d_in[6];
    float* out = (float*)d_out;

    float *pq, *pk, *pv, *ovh;
    cudaGetSymbolAddress((void**)&pq,  g_pq);
    cudaGetSymbolAddress((void**)&pk,  g_pk);
    cudaGetSymbolAddress((void**)&pv,  g_pv);
    cudaGetSymbolAddress((void**)&ovh, g_ovh);

    // QKV projections with fused sigmoid + head scatter
    sgemm_kernel<1><<<dim3(256 / 64, MROWS / 64), 256>>>(hs, Wq, pq, MROWS, NH * QKB, DD, QKB);
    sgemm_kernel<1><<<dim3(64 / 64,  MROWS / 64), 256>>>(hs, Wk, pk, MROWS, NKV * QKB, DD, QKB);
    sgemm_kernel<1><<<dim3(128 / 64, MROWS / 64), 256>>>(hs, Wv, pv, MROWS, NKV * VB, DD, VB);

    // Causal streaming attention + value-embedding epilogue
    rosa_attn_kernel<<<dim3(SS / ATT_BM, NH, BB), ATT_BM>>>(pq, pk, pv, e0, e1, ovh);

    // Output projection
    sgemm_kernel<0><<<dim3(DD / 64, MROWS / 64), 256>>>(ovh, Wo, out, MROWS, DD, NH * VB, 0);
}

// round 6
// speedup vs baseline: 1.5291x; 1.5291x over previous
#include <cuda_runtime.h>
#include <cuda_bf16.h>
#include <math.h>

#define BB 2
#define SS 2048
#define DD 1024
#define NH 16
#define NKV 4
#define QKB 16
#define VB 32
#define NREP (NH / NKV)
#define MROWS (BB * SS)   // 4096

typedef unsigned int u32;
typedef unsigned short u16;
typedef unsigned long long u64;

// ---- packed f32x2 helpers (for the projection SGEMMs) ----
__device__ __forceinline__ u64 pack2(float lo, float hi) {
    u64 r; asm("mov.b64 %0, {%1, %2};" : "=l"(r) : "f"(lo), "f"(hi)); return r;
}
__device__ __forceinline__ void fma2(u64& d, u64 a, u64 b) {
    asm("fma.rn.f32x2 %0, %1, %2, %3;" : "=l"(d) : "l"(a), "l"(b), "l"(d));
}
__device__ __forceinline__ float2 unpack2(u64 v) {
    float2 f; asm("mov.b64 {%0, %1}, %2;" : "=f"(f.x), "=f"(f.y) : "l"(v)); return f;
}

// ---- bf16 split helpers ----
__device__ __forceinline__ void bsplit(float x, float& hi, float& lo) {
    float h = __bfloat162float(__float2bfloat16(x));
    hi = h; lo = x - h;
}
__device__ __forceinline__ u32 packbf2(float a, float b) {   // a -> low half
    __nv_bfloat162 t = __floats2bfloat162_rn(a, b);
    return *(u32*)&t;
}

// ---- mma.sync m16n8k16 bf16, f32 accum ----
__device__ __forceinline__ void mma16816(float c[4], const u32 a[4], const u32 b[2]) {
    asm volatile(
        "mma.sync.aligned.m16n8k16.row.col.f32.bf16.bf16.f32 "
        "{%0,%1,%2,%3}, {%4,%5,%6,%7}, {%8,%9}, {%0,%1,%2,%3};"
        : "+f"(c[0]), "+f"(c[1]), "+f"(c[2]), "+f"(c[3])
        : "r"(a[0]), "r"(a[1]), "r"(a[2]), "r"(a[3]), "r"(b[0]), "r"(b[1]));
}

// ---- scratch (__device__ globals; no allocation allowed) ----
// __align__(16): several of these are accessed through float4* casts.
__device__ __align__(16) float g_pq[MROWS * NH * QKB];
__device__ __align__(16) float g_pk[MROWS * NKV * QKB];
__device__ __align__(16) float g_pv[MROWS * NKV * VB];
__device__ __align__(16) float g_ovh[MROWS * NH * VB];
__device__ __align__(16) u16 g_qmh[BB * NH * SS * QKB];
__device__ __align__(16) u16 g_qml[BB * NH * SS * QKB];
__device__ __align__(16) float g_qc[BB * NH * SS];
__device__ __align__(16) u16 g_kh[BB * NKV * SS * QKB];
__device__ __align__(16) u16 g_kl[BB * NKV * SS * QKB];
__device__ __align__(16) u16 g_vth[BB * NKV * VB * SS];
__device__ __align__(16) u16 g_vtl[BB * NKV * VB * SS];

// ---------------------------------------------------------------------------
// SGEMM: C[M,N] = A[M,K] @ W[K,N], row-major, optional sigmoid epilogue.
// 64x64 tile, Ktile 16, 256 threads, 4x4/thread, packed f32x2 inner product.
// ---------------------------------------------------------------------------
template <int SIG>
__global__ void __launch_bounds__(256) sgemm_kernel(
    const float* __restrict__ A, const float* __restrict__ W,
    float* __restrict__ C, int M, int N, int K)
{
    __shared__ __align__(16) float As[16][64];
    __shared__ __align__(16) float Bs[16][64];

    const int tid = threadIdx.x;
    const int tx = tid & 15;
    const int ty = tid >> 4;
    const int row0 = blockIdx.y * 64;
    const int col0 = blockIdx.x * 64;

    const int arow = tid >> 2;
    const int acol = (tid & 3) * 4;
    const int brow = tid >> 4;
    const int bcol = (tid & 15) * 4;

    const float* Aptr = A + (size_t)(row0 + arow) * K + acol;
    const float* Wptr = W + (size_t)brow * N + col0 + bcol;

    u64 acc2[4][2];
    const u64 z = pack2(0.f, 0.f);
#pragma unroll
    for (int i = 0; i < 4; i++) { acc2[i][0] = z; acc2[i][1] = z; }

    for (int kk = 0; kk < K; kk += 16) {
        float4 av = *(const float4*)Aptr;  Aptr += 16;
        float4 bv = *(const float4*)Wptr;  Wptr += (size_t)16 * N;

        As[acol + 0][arow] = av.x;
        As[acol + 1][arow] = av.y;
        As[acol + 2][arow] = av.z;
        As[acol + 3][arow] = av.w;
        *(float4*)&Bs[brow][bcol] = bv;
        __syncthreads();

#pragma unroll
        for (int k = 0; k < 16; k++) {
            float4 a4 = *(const float4*)&As[k][ty * 4];
            ulonglong2 bb = *(const ulonglong2*)&Bs[k][tx * 4];
            float am[4] = {a4.x, a4.y, a4.z, a4.w};
#pragma unroll
            for (int i = 0; i < 4; i++) {
                u64 ai = pack2(am[i], am[i]);
                fma2(acc2[i][0], ai, bb.x);
                fma2(acc2[i][1], ai, bb.y);
            }
        }
        __syncthreads();
    }

#pragma unroll
    for (int i = 0; i < 4; i++) {
        int m = row0 + ty * 4 + i;
        float2 c0 = unpack2(acc2[i][0]);
        float2 c1 = unpack2(acc2[i][1]);
        float4 st = make_float4(c0.x, c0.y, c1.x, c1.y);
        if (SIG) {
            st.x = 1.f / (1.f + __expf(-st.x));
            st.y = 1.f / (1.f + __expf(-st.y));
            st.z = 1.f / (1.f + __expf(-st.z));
            st.w = 1.f / (1.f + __expf(-st.w));
        }
        *(float4*)&C[(size_t)m * N + col0 + tx * 4] = st;
    }
}

// ---------------------------------------------------------------------------
// Convert Q/K rows to split-bf16 [b,head,s,16]; for Q also apply 2x-1 and
// emit c = 16 - sum(pq). One thread = one 16-wide row.
// ---------------------------------------------------------------------------
template <bool ISQ>
__global__ void convqk_kernel(const float* __restrict__ src,
                              u16* __restrict__ dh, u16* __restrict__ dl,
                              float* __restrict__ qc, int nheads)
{
    int tid = blockIdx.x * blockDim.x + threadIdx.x;   // = ms*nheads + h
    int total = MROWS * nheads;
    if (tid >= total) return;
    int h = tid % nheads;
    int ms = tid / nheads;
    int b = ms / SS, s = ms - b * SS;

    const float4* p = (const float4*)(src + (size_t)tid * QKB);
    float c = (float)QKB;
    __align__(16) u32 oh[8];
    __align__(16) u32 ol[8];
#pragma unroll
    for (int i = 0; i < 4; i++) {
        float4 v = p[i];
        float xs[4] = {v.x, v.y, v.z, v.w};
        float hs[4], ls[4];
#pragma unroll
        for (int j = 0; j < 4; j++) {
            float x = xs[j];
            if (ISQ) { c -= x; x = 2.f * x - 1.f; }
            bsplit(x, hs[j], ls[j]);
        }
        oh[i * 2]     = packbf2(hs[0], hs[1]);
        oh[i * 2 + 1] = packbf2(hs[2], hs[3]);
        ol[i * 2]     = packbf2(ls[0], ls[1]);
        ol[i * 2 + 1] = packbf2(ls[2], ls[3]);
    }
    size_t orow = ((size_t)(b * nheads + h) * SS + s) * QKB;
    ((float4*)(dh + orow))[0] = *(float4*)&oh[0];
    ((float4*)(dh + orow))[1] = *(float4*)&oh[4];
    ((float4*)(dl + orow))[0] = *(float4*)&ol[0];
    ((float4*)(dl + orow))[1] = *(float4*)&ol[4];
    if (ISQ) qc[(size_t)(b * nheads + h) * SS + s] = c;
}

// ---------------------------------------------------------------------------
// Transpose + split V: pv flat [b*S+s][kv*32+vd] -> [b,kv,vd,S] bf16 hi/lo.
// ---------------------------------------------------------------------------
__global__ void __launch_bounds__(256) convv_kernel(
    const float* __restrict__ pv, u16* __restrict__ vth, u16* __restrict__ vtl)
{
    __shared__ __align__(16) float tile[64][33];
    const int s0 = blockIdx.x * 64;
    const int kv = blockIdx.y;
    const int b  = blockIdx.z;
    const int t  = threadIdx.x;

    {   // load 64x32, coalesced
        int sl = t >> 2, vg = (t & 3) * 8;
        const float4* src = (const float4*)(pv + ((size_t)(b * SS + s0 + sl)) * (NKV * VB)
                                            + kv * VB + vg);
        float4 v0 = src[0], v1 = src[1];
        tile[sl][vg + 0] = v0.x; tile[sl][vg + 1] = v0.y;
        tile[sl][vg + 2] = v0.z; tile[sl][vg + 3] = v0.w;
        tile[sl][vg + 4] = v1.x; tile[sl][vg + 5] = v1.y;
        tile[sl][vg + 6] = v1.z; tile[sl][vg + 7] = v1.w;
    }
    __syncthreads();
    {   // write transposed, split
        int vd = t >> 3, sc = (t & 7) * 8;
        __align__(16) u32 oh[4];
        __align__(16) u32 ol[4];
#pragma unroll
        for (int j = 0; j < 4; j++) {
            float x0 = tile[sc + 2 * j][vd], x1 = tile[sc + 2 * j + 1][vd];
            float h0, l0, h1, l1;
            bsplit(x0, h0, l0); bsplit(x1, h1, l1);
            oh[j] = packbf2(h0, h1);
            ol[j] = packbf2(l0, l1);
        }
        size_t orow = (((size_t)(b * NKV + kv) * VB + vd) * SS) + s0 + sc;
        *(float4*)(vth + orow) = *(float4*)&oh[0];
        *(float4*)(vtl + orow) = *(float4*)&ol[0];
    }
}

// ---------------------------------------------------------------------------
// Flash-style causal attention on tensor cores (mma.sync bf16, hi/lo split).
// CTA = 128 queries (8 warps x m16), key tiles of 128. No online max needed:
// scores in [0,16]. P fed fragment-to-fragment from the score accumulators.
// ---------------------------------------------------------------------------
#define QM 128
#define BN 128
#define SKP 24            // K smem row pad (halves): 48B stride, conflict-free
#define SVP (BN + 8)      // V smem row pad: 272B stride, conflict-free

__global__ void __launch_bounds__(256) rosa_attn_mma(
    const u16* __restrict__ qmh, const u16* __restrict__ qml,
    const float* __restrict__ qc,
    const u16* __restrict__ kh, const u16* __restrict__ kl,
    const u16* __restrict__ vth, const u16* __restrict__ vtl,
    const float* __restrict__ e0, const float* __restrict__ e1,
    float* __restrict__ ovh)
{
    __shared__ __align__(16) u16 skh[BN][SKP];
    __shared__ __align__(16) u16 skl[BN][SKP];
    __shared__ __align__(16) u16 svh[VB][SVP];
    __shared__ __align__(16) u16 svl[VB][SVP];

    const int qblk = blockIdx.x, h = blockIdx.y, b = blockIdx.z;
    const int kv = h / NREP;
    const int tid = threadIdx.x, warp = tid >> 5, lane = tid & 31;
    const int g = lane >> 2, tg = lane & 3;
    const int qw0 = qblk * QM + warp * 16;

    // A fragments (queries), loaded once
    const u16* qbh = qmh + ((size_t)(b * NH + h) * SS) * QKB;
    const u16* qbl = qml + ((size_t)(b * NH + h) * SS) * QKB;
    size_t a0 = (size_t)(qw0 + g) * QKB + tg * 2;
    u32 a_hi[4], a_lo[4];
    a_hi[0] = *(const u32*)(qbh + a0);
    a_hi[1] = *(const u32*)(qbh + a0 + 8 * QKB);
    a_hi[2] = *(const u32*)(qbh + a0 + 8);
    a_hi[3] = *(const u32*)(qbh + a0 + 8 * QKB + 8);
    a_lo[0] = *(const u32*)(qbl + a0);
    a_lo[1] = *(const u32*)(qbl + a0 + 8 * QKB);
    a_lo[2] = *(const u32*)(qbl + a0 + 8);
    a_lo[3] = *(const u32*)(qbl + a0 + 8 * QKB + 8);
    const float* qcb = qc + (size_t)(b * NH + h) * SS + qw0;
    const float c0 = qcb[g], c1 = qcb[g + 8];
    const int qg0 = qw0 + g, qg1 = qg0 + 8;

    float num[4][4];
#pragma unroll
    for (int i = 0; i < 4; i++)
#pragma unroll
        for (int j = 0; j < 4; j++) num[i][j] = 0.f;
    float den0 = 0.f, den1 = 0.f;

    const u16* kbh = kh + ((size_t)(b * NKV + kv) * SS) * QKB;
    const u16* kbl = kl + ((size_t)(b * NKV + kv) * SS) * QKB;
    const u16* vbh = vth + ((size_t)(b * NKV + kv) * VB) * SS;
    const u16* vbl = vtl + ((size_t)(b * NKV + kv) * VB) * SS;

    for (int t0 = 0; t0 <= qblk; t0++) {
        {   // K tile: 128 rows x 16 halves (hi: threads 0-127, lo: 128-255)
            int r = tid & 127;
            const u16* src = ((tid < 128) ? kbh : kbl) + ((size_t)(t0 * BN + r)) * QKB;
            u16 (*dst)[SKP] = (tid < 128) ? skh : skl;
            float4 v0 = ((const float4*)src)[0];
            float4 v1 = ((const float4*)src)[1];
            *(float4*)&dst[r][0] = v0;
            *(float4*)&dst[r][8] = v1;
        }
#pragma unroll
        for (int i = 0; i < 2; i++) {   // V tile: 32 rows x 128 halves, hi+lo
            int idx = tid + i * 256;    // 0..511 -> (row, 16B-chunk)
            int row = idx >> 4, c4 = idx & 15;
            *(float4*)&svh[row][c4 * 8] =
                *((const float4*)(vbh + (size_t)row * SS + t0 * BN) + c4);
            *(float4*)&svl[row][c4 * 8] =
                *((const float4*)(vbl + (size_t)row * SS + t0 * BN) + c4);
        }
        __syncthreads();

        const bool diag = (t0 == qblk);
        for (int kc = 0; kc < 8; kc++) {
            float sc[2][4];
#pragma unroll
            for (int hf = 0; hf < 2; hf++) {
                int n8 = kc * 16 + hf * 8;
                u32 bh_[2], bl_[2];
                const u16* kr  = &skh[n8 + g][tg * 2];
                const u16* krl = &skl[n8 + g][tg * 2];
                bh_[0] = *(const u32*)kr;        bh_[1] = *(const u32*)(kr + 8);
                bl_[0] = *(const u32*)krl;       bl_[1] = *(const u32*)(krl + 8);
                float cc[4] = {0.f, 0.f, 0.f, 0.f};
                mma16816(cc, a_hi, bh_);
                mma16816(cc, a_hi, bl_);
                mma16816(cc, a_lo, bh_);
                sc[hf][0] = cc[0]; sc[hf][1] = cc[1];
                sc[hf][2] = cc[2]; sc[hf][3] = cc[3];
            }
            // exp + causal mask + split -> A fragments for PV
            u32 Ah[4], Al[4];
#pragma unroll
            for (int hf = 0; hf < 2; hf++) {
                int kb = t0 * BN + kc * 16 + hf * 8 + tg * 2;
                float p0 = __expf(sc[hf][0] + c0);
                float p1 = __expf(sc[hf][1] + c0);
                float p2 = __expf(sc[hf][2] + c1);
                float p3 = __expf(sc[hf][3] + c1);
                if (diag) {
                    if (kb     > qg0) p0 = 0.f;
                    if (kb + 1 > qg0) p1 = 0.f;
                    if (kb     > qg1) p2 = 0.f;
                    if (kb + 1 > qg1) p3 = 0.f;
                }
                den0 += p0 + p1;
                den1 += p2 + p3;
                float h0, l0, h1, l1, h2, l2, h3, l3;
                bsplit(p0, h0, l0); bsplit(p1, h1, l1);
                bsplit(p2, h2, l2); bsplit(p3, h3, l3);
                Ah[hf * 2]     = packbf2(h0, h1);
                Ah[hf * 2 + 1] = packbf2(h2, h3);
                Al[hf * 2]     = packbf2(l0, l1);
                Al[hf * 2 + 1] = packbf2(l2, l3);
            }
            // PV: num += P @ V  (V transposed in smem)
#pragma unroll
            for (int vt = 0; vt < 4; vt++) {
                u32 bvh[2], bvl[2];
                const u16* vr  = &svh[vt * 8 + g][kc * 16 + tg * 2];
                const u16* vrl = &svl[vt * 8 + g][kc * 16 + tg * 2];
                bvh[0] = *(const u32*)vr;   bvh[1] = *(const u32*)(vr + 8);
                bvl[0] = *(const u32*)vrl;  bvl[1] = *(const u32*)(vrl + 8);
                mma16816(num[vt], Ah, bvh);
                mma16816(num[vt], Ah, bvl);
                mma16816(num[vt], Al, bvh);
            }
        }
        __syncthreads();
    }

    // reduce den across the 4 lanes sharing a row-group
    den0 += __shfl_xor_sync(0xffffffffu, den0, 1);
    den0 += __shfl_xor_sync(0xffffffffu, den0, 2);
    den1 += __shfl_xor_sync(0xffffffffu, den1, 1);
    den1 += __shfl_xor_sync(0xffffffffu, den1, 2);
    const float inv0 = 1.f / den0, inv1 = 1.f / den1;

#pragma unroll
    for (int vt = 0; vt < 4; vt++) {
        int vd = vt * 8 + tg * 2;
        float a00 = e0[h * VB + vd],     b00 = e1[h * VB + vd];
        float a01 = e0[h * VB + vd + 1], b01 = e1[h * VB + vd + 1];
        float2 o0, o1;
        o0.x = fmaf(b00 - a00, num[vt][0] * inv0, a00);
        o0.y = fmaf(b01 - a01, num[vt][1] * inv0, a01);
        o1.x = fmaf(b00 - a00, num[vt][2] * inv1, a00);
        o1.y = fmaf(b01 - a01, num[vt][3] * inv1, a01);
        *(float2*)&ovh[((size_t)(b * SS + qg0) * NH + h) * VB + vd] = o0;
        *(float2*)&ovh[((size_t)(b * SS + qg1) * NH + h) * VB + vd] = o1;
    }
}

// ---------------------------------------------------------------------------
extern "C" void kernel_launch(void* const* d_in, const int* in_sizes, int n_in,
                              void* d_out, int out_size)
{
    const float* hs = (const float*)d_in[0];
    const float* Wq = (const float*)d_in[1];
    const float* Wk = (const float*)d_in[2];
    const float* Wv = (const float*)d_in[3];
    const float* Wo = (const float*)d_in[4];
    const float* e0 = (const float*)d_in[5];
    const float* e1 = (const float*)d_in[6];
    float* out = (float*)d_out;

    float *pq, *pk, *pv, *ovh, *qcp;
    u16 *qmh, *qml, *kh_, *kl_, *vth, *vtl;
    cudaGetSymbolAddress((void**)&pq,  g_pq);
    cudaGetSymbolAddress((void**)&pk,  g_pk);
    cudaGetSymbolAddress((void**)&pv,  g_pv);
    cudaGetSymbolAddress((void**)&ovh, g_ovh);
    cudaGetSymbolAddress((void**)&qcp, g_qc);
    cudaGetSymbolAddress((void**)&qmh, g_qmh);
    cudaGetSymbolAddress((void**)&qml, g_qml);
    cudaGetSymbolAddress((void**)&kh_, g_kh);
    cudaGetSymbolAddress((void**)&kl_, g_kl);
    cudaGetSymbolAddress((void**)&vth, g_vth);
    cudaGetSymbolAddress((void**)&vtl, g_vtl);

    // QKV projections (sigmoid fused), flat row-major
    sgemm_kernel<1><<<dim3(256 / 64, MROWS / 64), 256>>>(hs, Wq, pq, MROWS, NH * QKB, DD);
    sgemm_kernel<1><<<dim3(64 / 64,  MROWS / 64), 256>>>(hs, Wk, pk, MROWS, NKV * QKB, DD);
    sgemm_kernel<1><<<dim3(128 / 64, MROWS / 64), 256>>>(hs, Wv, pv, MROWS, NKV * VB, DD);

    // Convert to split-bf16 operand layouts
    convqk_kernel<true ><<<(MROWS * NH  + 127) / 128, 128>>>(pq, qmh, qml, qcp, NH);
    convqk_kernel<false><<<(MROWS * NKV + 127) / 128, 128>>>(pk, kh_, kl_, nullptr, NKV);
    convv_kernel<<<dim3(SS / 64, NKV, BB), 256>>>(pv, vth, vtl);

    // Tensor-core causal attention + value-embedding epilogue
    rosa_attn_mma<<<dim3(SS / QM, NH, BB), 256>>>(qmh, qml, qcp, kh_, kl_, vth, vtl,
                                                  e0, e1, ovh);

    // Output projection
    sgemm_kernel<0><<<dim3(DD / 64, MROWS / 64), 256>>>(ovh, Wo, out, MROWS, DD, NH * VB);
}

// round 8
// speedup vs baseline: 2.4033x; 1.5717x over previous
#include <cuda_runtime.h>
#include <cuda_bf16.h>
#include <math.h>

#define BB 2
#define SS 2048
#define DD 1024
#define NH 16
#define NKV 4
#define QKB 16
#define VB 32
#define NREP (NH / NKV)
#define MROWS (BB * SS)       // 4096
#define NQKV (NH * QKB + NKV * QKB + NKV * VB)   // 256+64+128 = 448
#define KO (NH * VB)          // 512

typedef unsigned int u32;
typedef unsigned short u16;

// ---- bf16 split helpers ----
__device__ __forceinline__ void bsplit(float x, float& hi, float& lo) {
    float h = __bfloat162float(__float2bfloat16(x));
    hi = h; lo = x - h;
}
__device__ __forceinline__ u32 packbf2(float a, float b) {   // a -> low half
    __nv_bfloat162 t = __floats2bfloat162_rn(a, b);
    return *(u32*)&t;
}

// ---- mma.sync m16n8k16 bf16, f32 accum (fragment mappings verified R6) ----
__device__ __forceinline__ void mma16816(float c[4], const u32 a[4], const u32 b[2]) {
    asm volatile(
        "mma.sync.aligned.m16n8k16.row.col.f32.bf16.bf16.f32 "
        "{%0,%1,%2,%3}, {%4,%5,%6,%7}, {%8,%9}, {%0,%1,%2,%3};"
        : "+f"(c[0]), "+f"(c[1]), "+f"(c[2]), "+f"(c[3])
        : "r"(a[0]), "r"(a[1]), "r"(a[2]), "r"(a[3]), "r"(b[0]), "r"(b[1]));
}

// ---- scratch (__device__ globals; no allocation allowed) ----
__device__ __align__(16) u16 g_hsh[MROWS * DD];          // hs split hi   8MB
__device__ __align__(16) u16 g_hsl[MROWS * DD];          //          lo   8MB
__device__ __align__(16) u16 g_wth[NQKV * DD];           // [448][1024] Wqkv^T hi
__device__ __align__(16) u16 g_wtl[NQKV * DD];
__device__ __align__(16) u16 g_woth[DD * KO];            // [1024][512] Wo^T hi
__device__ __align__(16) u16 g_wotl[DD * KO];
__device__ __align__(16) float g_qkv[MROWS * NQKV];      // sigmoid(QKV) 7MB
__device__ __align__(16) u16 g_ovhh[MROWS * KO];         // attention out split
__device__ __align__(16) u16 g_ovhl[MROWS * KO];
__device__ __align__(16) u16 g_qmh[BB * NH * SS * QKB];
__device__ __align__(16) u16 g_qml[BB * NH * SS * QKB];
__device__ __align__(16) float g_qc[BB * NH * SS];
__device__ __align__(16) u16 g_kh[BB * NKV * SS * QKB];
__device__ __align__(16) u16 g_kl[BB * NKV * SS * QKB];
__device__ __align__(16) u16 g_vth[BB * NKV * VB * SS];
__device__ __align__(16) u16 g_vtl[BB * NKV * VB * SS];

// ---------------------------------------------------------------------------
// Elementwise fp32 -> split bf16 (hi/lo). 8 elems/thread, all float4.
// ---------------------------------------------------------------------------
__global__ void convert_split_kernel(const float* __restrict__ src,
                                     u16* __restrict__ dh, u16* __restrict__ dl,
                                     int total)
{
    int idx = blockIdx.x * blockDim.x + threadIdx.x;
    int base = idx * 8;
    if (base >= total) return;
    float4 v0 = *(const float4*)(src + base);
    float4 v1 = *(const float4*)(src + base + 4);
    float xs[8] = {v0.x, v0.y, v0.z, v0.w, v1.x, v1.y, v1.z, v1.w};
    __align__(16) u32 oh[4];
    __align__(16) u32 ol[4];
#pragma unroll
    for (int i = 0; i < 4; i++) {
        float h0, l0, h1, l1;
        bsplit(xs[2 * i], h0, l0);
        bsplit(xs[2 * i + 1], h1, l1);
        oh[i] = packbf2(h0, h1);
        ol[i] = packbf2(l0, l1);
    }
    *(float4*)(dh + base) = *(float4*)&oh[0];
    *(float4*)(dl + base) = *(float4*)&ol[0];
}

// ---------------------------------------------------------------------------
// Transpose + split a weight: src fp32 [K][N] -> dst bf16 [nOff+n][K].
// 32x32 smem tiles. dstStride = K.
// ---------------------------------------------------------------------------
__global__ void __launch_bounds__(256) transpose_split_kernel(
    const float* __restrict__ src, int K, int N,
    u16* __restrict__ dh, u16* __restrict__ dl, int dstStride, int nOff)
{
    __shared__ __align__(16) float tile[32][33];
    const int n0 = blockIdx.x * 32;
    const int k0 = blockIdx.y * 32;
    const int t = threadIdx.x;
    {
        int r = t >> 3, c = (t & 7) * 4;
        float4 v = *(const float4*)(src + (size_t)(k0 + r) * N + n0 + c);
        tile[r][c + 0] = v.x; tile[r][c + 1] = v.y;
        tile[r][c + 2] = v.z; tile[r][c + 3] = v.w;
    }
    __syncthreads();
    {
        int col = t >> 3, k4 = (t & 7) * 4;   // col = local n, k4 = local k
        __align__(8) u32 oh[2];
        __align__(8) u32 ol[2];
#pragma unroll
        for (int i = 0; i < 2; i++) {
            float h0, l0, h1, l1;
            bsplit(tile[k4 + 2 * i][col], h0, l0);
            bsplit(tile[k4 + 2 * i + 1][col], h1, l1);
            oh[i] = packbf2(h0, h1);
            ol[i] = packbf2(l0, l1);
        }
        size_t o = (size_t)(nOff + n0 + col) * dstStride + k0 + k4;
        *(float2*)(dh + o) = *(float2*)&oh[0];
        *(float2*)(dl + o) = *(float2*)&ol[0];
    }
}

// ---------------------------------------------------------------------------
// Split-bf16 tensor-core GEMM: C[M,N] = A[M,K] @ B^T  (B stored [N][K]).
// Tile 128x64x32, 256 threads, warp tile 32x32 (2 m16 x 4 n8), 3 MMAs per
// product (hi*hi + hi*lo + lo*hi). SIG=1: sigmoid epilogue.
// ---------------------------------------------------------------------------
template <int SIG>
__global__ void __launch_bounds__(256) bgemm_kernel(
    const u16* __restrict__ Ah, const u16* __restrict__ Al,
    const u16* __restrict__ Bh, const u16* __restrict__ Bl,
    float* __restrict__ C, int M, int N, int K)
{
    __shared__ __align__(16) u16 sAh[128][40];
    __shared__ __align__(16) u16 sAl[128][40];
    __shared__ __align__(16) u16 sBh[64][40];
    __shared__ __align__(16) u16 sBl[64][40];

    const int tid = threadIdx.x, warp = tid >> 5, lane = tid & 31;
    const int g = lane >> 2, tg = lane & 3;
    const int wm = warp >> 1, wn = warp & 1;
    const int row0 = blockIdx.y * 128, col0 = blockIdx.x * 64;

    float acc[2][4][4];
#pragma unroll
    for (int mt = 0; mt < 2; mt++)
#pragma unroll
        for (int nt = 0; nt < 4; nt++)
#pragma unroll
            for (int i = 0; i < 4; i++) acc[mt][nt][i] = 0.f;

    for (int k0 = 0; k0 < K; k0 += 32) {
#pragma unroll
        for (int i = 0; i < 2; i++) {      // A tile: 128 rows x 32 halves
            int ch = tid + i * 256;
            int r = ch >> 2, c = (ch & 3) * 8;
            *(float4*)&sAh[r][c] = *(const float4*)(Ah + (size_t)(row0 + r) * K + k0 + c);
            *(float4*)&sAl[r][c] = *(const float4*)(Al + (size_t)(row0 + r) * K + k0 + c);
        }
        {                                   // B tile: 64 rows x 32 halves
            int r = tid >> 2, c = (tid & 3) * 8;
            *(float4*)&sBh[r][c] = *(const float4*)(Bh + (size_t)(col0 + r) * K + k0 + c);
            *(float4*)&sBl[r][c] = *(const float4*)(Bl + (size_t)(col0 + r) * K + k0 + c);
        }
        __syncthreads();

#pragma unroll
        for (int k16 = 0; k16 < 2; k16++) {
            const int kb = k16 * 16 + tg * 2;
            u32 ah[2][4], al[2][4];
#pragma unroll
            for (int mt = 0; mt < 2; mt++) {
                int ar = wm * 32 + mt * 16 + g;
                ah[mt][0] = *(const u32*)&sAh[ar][kb];
                ah[mt][1] = *(const u32*)&sAh[ar + 8][kb];
                ah[mt][2] = *(const u32*)&sAh[ar][kb + 8];
                ah[mt][3] = *(const u32*)&sAh[ar + 8][kb + 8];
                al[mt][0] = *(const u32*)&sAl[ar][kb];
                al[mt][1] = *(const u32*)&sAl[ar + 8][kb];
                al[mt][2] = *(const u32*)&sAl[ar][kb + 8];
                al[mt][3] = *(const u32*)&sAl[ar + 8][kb + 8];
            }
#pragma unroll
            for (int nt = 0; nt < 4; nt++) {
                int br = wn * 32 + nt * 8 + g;
                u32 bh[2], bl[2];
                bh[0] = *(const u32*)&sBh[br][kb];
                bh[1] = *(const u32*)&sBh[br][kb + 8];
                bl[0] = *(const u32*)&sBl[br][kb];
                bl[1] = *(const u32*)&sBl[br][kb + 8];
#pragma unroll
                for (int mt = 0; mt < 2; mt++) {
                    mma16816(acc[mt][nt], ah[mt], bh);
                    mma16816(acc[mt][nt], ah[mt], bl);
                    mma16816(acc[mt][nt], al[mt], bh);
                }
            }
        }
        __syncthreads();
    }

#pragma unroll
    for (int mt = 0; mt < 2; mt++) {
        int m0 = row0 + wm * 32 + mt * 16 + g;
#pragma unroll
        for (int nt = 0; nt < 4; nt++) {
            int n = col0 + wn * 32 + nt * 8 + tg * 2;
            float2 v0 = make_float2(acc[mt][nt][0], acc[mt][nt][1]);
            float2 v1 = make_float2(acc[mt][nt][2], acc[mt][nt][3]);
            if (SIG) {
                v0.x = 1.f / (1.f + __expf(-v0.x));
                v0.y = 1.f / (1.f + __expf(-v0.y));
                v1.x = 1.f / (1.f + __expf(-v1.x));
                v1.y = 1.f / (1.f + __expf(-v1.y));
            }
            *(float2*)&C[(size_t)m0 * N + n] = v0;
            *(float2*)&C[(size_t)(m0 + 8) * N + n] = v1;
        }
    }
}

// ---------------------------------------------------------------------------
// Convert Q/K rows (from the fused qkv buffer) to split-bf16 [b,head,s,16];
// for Q also apply 2x-1 and emit c = 16 - sum(pq).
// ---------------------------------------------------------------------------
template <bool ISQ>
__global__ void convqk_kernel(const float* __restrict__ src, int srcStride, int colOff,
                              u16* __restrict__ dh, u16* __restrict__ dl,
                              float* __restrict__ qc, int nheads)
{
    int tid = blockIdx.x * blockDim.x + threadIdx.x;   // = ms*nheads + h
    int total = MROWS * nheads;
    if (tid >= total) return;
    int h = tid % nheads;
    int ms = tid / nheads;
    int b = ms / SS, s = ms - b * SS;

    const float4* p = (const float4*)(src + (size_t)ms * srcStride + colOff + h * QKB);
    float c = (float)QKB;
    __align__(16) u32 oh[8];
    __align__(16) u32 ol[8];
#pragma unroll
    for (int i = 0; i < 4; i++) {
        float4 v = p[i];
        float xs[4] = {v.x, v.y, v.z, v.w};
        float hs[4], ls[4];
#pragma unroll
        for (int j = 0; j < 4; j++) {
            float x = xs[j];
            if (ISQ) { c -= x; x = 2.f * x - 1.f; }
            bsplit(x, hs[j], ls[j]);
        }
        oh[i * 2]     = packbf2(hs[0], hs[1]);
        oh[i * 2 + 1] = packbf2(hs[2], hs[3]);
        ol[i * 2]     = packbf2(ls[0], ls[1]);
        ol[i * 2 + 1] = packbf2(ls[2], ls[3]);
    }
    size_t orow = ((size_t)(b * nheads + h) * SS + s) * QKB;
    ((float4*)(dh + orow))[0] = *(float4*)&oh[0];
    ((float4*)(dh + orow))[1] = *(float4*)&oh[4];
    ((float4*)(dl + orow))[0] = *(float4*)&ol[0];
    ((float4*)(dl + orow))[1] = *(float4*)&ol[4];
    if (ISQ) qc[(size_t)(b * nheads + h) * SS + s] = c;
}

// ---------------------------------------------------------------------------
// Transpose + split V (from qkv buffer) -> [b,kv,vd,S] bf16 hi/lo.
// ---------------------------------------------------------------------------
#define VOFF (NH * QKB + NKV * QKB)   // 320

__global__ void __launch_bounds__(256) convv_kernel(
    const float* __restrict__ qkv, u16* __restrict__ vth, u16* __restrict__ vtl)
{
    __shared__ __align__(16) float tile[64][33];
    const int s0 = blockIdx.x * 64;
    const int kv = blockIdx.y;
    const int b  = blockIdx.z;
    const int t  = threadIdx.x;

    {   // load 64x32, coalesced
        int sl = t >> 2, vg = (t & 3) * 8;
        const float4* src = (const float4*)(qkv + ((size_t)(b * SS + s0 + sl)) * NQKV
                                            + VOFF + kv * VB + vg);
        float4 v0 = src[0], v1 = src[1];
        tile[sl][vg + 0] = v0.x; tile[sl][vg + 1] = v0.y;
        tile[sl][vg + 2] = v0.z; tile[sl][vg + 3] = v0.w;
        tile[sl][vg + 4] = v1.x; tile[sl][vg + 5] = v1.y;
        tile[sl][vg + 6] = v1.z; tile[sl][vg + 7] = v1.w;
    }
    __syncthreads();
    {   // write transposed, split
        int vd = t >> 3, sc = (t & 7) * 8;
        __align__(16) u32 oh[4];
        __align__(16) u32 ol[4];
#pragma unroll
        for (int j = 0; j < 4; j++) {
            float x0 = tile[sc + 2 * j][vd], x1 = tile[sc + 2 * j + 1][vd];
            float h0, l0, h1, l1;
            bsplit(x0, h0, l0); bsplit(x1, h1, l1);
            oh[j] = packbf2(h0, h1);
            ol[j] = packbf2(l0, l1);
        }
        size_t orow = (((size_t)(b * NKV + kv) * VB + vd) * SS) + s0 + sc;
        *(float4*)(vth + orow) = *(float4*)&oh[0];
        *(float4*)(vtl + orow) = *(float4*)&ol[0];
    }
}

// ---------------------------------------------------------------------------
// Flash-style causal attention on tensor cores (mma.sync bf16, hi/lo split).
// CTA = 128 queries (8 warps x m16), key tiles of 128. Scores in [0,16]:
// no online max. Epilogue emits split-bf16 ovh for the O-projection GEMM.
// ---------------------------------------------------------------------------
#define QM 128
#define BN 128
#define SKP 24
#define SVP (BN + 8)

__global__ void __launch_bounds__(256) rosa_attn_mma(
    const u16* __restrict__ qmh, const u16* __restrict__ qml,
    const float* __restrict__ qc,
    const u16* __restrict__ kh, const u16* __restrict__ kl,
    const u16* __restrict__ vth, const u16* __restrict__ vtl,
    const float* __restrict__ e0, const float* __restrict__ e1,
    u16* __restrict__ ovhh, u16* __restrict__ ovhl)
{
    __shared__ __align__(16) u16 skh[BN][SKP];
    __shared__ __align__(16) u16 skl[BN][SKP];
    __shared__ __align__(16) u16 svh[VB][SVP];
    __shared__ __align__(16) u16 svl[VB][SVP];

    const int qblk = blockIdx.x, h = blockIdx.y, b = blockIdx.z;
    const int kv = h / NREP;
    const int tid = threadIdx.x, warp = tid >> 5, lane = tid & 31;
    const int g = lane >> 2, tg = lane & 3;
    const int qw0 = qblk * QM + warp * 16;

    const u16* qbh = qmh + ((size_t)(b * NH + h) * SS) * QKB;
    const u16* qbl = qml + ((size_t)(b * NH + h) * SS) * QKB;
    size_t a0 = (size_t)(qw0 + g) * QKB + tg * 2;
    u32 a_hi[4], a_lo[4];
    a_hi[0] = *(const u32*)(qbh + a0);
    a_hi[1] = *(const u32*)(qbh + a0 + 8 * QKB);
    a_hi[2] = *(const u32*)(qbh + a0 + 8);
    a_hi[3] = *(const u32*)(qbh + a0 + 8 * QKB + 8);
    a_lo[0] = *(const u32*)(qbl + a0);
    a_lo[1] = *(const u32*)(qbl + a0 + 8 * QKB);
    a_lo[2] = *(const u32*)(qbl + a0 + 8);
    a_lo[3] = *(const u32*)(qbl + a0 + 8 * QKB + 8);
    const float* qcb = qc + (size_t)(b * NH + h) * SS + qw0;
    const float c0 = qcb[g], c1 = qcb[g + 8];
    const int qg0 = qw0 + g, qg1 = qg0 + 8;

    float num[4][4];
#pragma unroll
    for (int i = 0; i < 4; i++)
#pragma unroll
        for (int j = 0; j < 4; j++) num[i][j] = 0.f;
    float den0 = 0.f, den1 = 0.f;

    const u16* kbh = kh + ((size_t)(b * NKV + kv) * SS) * QKB;
    const u16* kbl = kl + ((size_t)(b * NKV + kv) * SS) * QKB;
    const u16* vbh = vth + ((size_t)(b * NKV + kv) * VB) * SS;
    const u16* vbl = vtl + ((size_t)(b * NKV + kv) * VB) * SS;

    for (int t0 = 0; t0 <= qblk; t0++) {
        {
            int r = tid & 127;
            const u16* src = ((tid < 128) ? kbh : kbl) + ((size_t)(t0 * BN + r)) * QKB;
            u16 (*dst)[SKP] = (tid < 128) ? skh : skl;
            float4 v0 = ((const float4*)src)[0];
            float4 v1 = ((const float4*)src)[1];
            *(float4*)&dst[r][0] = v0;
            *(float4*)&dst[r][8] = v1;
        }
#pragma unroll
        for (int i = 0; i < 2; i++) {
            int idx = tid + i * 256;
            int row = idx >> 4, c4 = idx & 15;
            *(float4*)&svh[row][c4 * 8] =
                *((const float4*)(vbh + (size_t)row * SS + t0 * BN) + c4);
            *(float4*)&svl[row][c4 * 8] =
                *((const float4*)(vbl + (size_t)row * SS + t0 * BN) + c4);
        }
        __syncthreads();

        const bool diag = (t0 == qblk);
        for (int kc = 0; kc < 8; kc++) {
            float sc[2][4];
#pragma unroll
            for (int hf = 0; hf < 2; hf++) {
                int n8 = kc * 16 + hf * 8;
                u32 bh_[2], bl_[2];
                const u16* kr  = &skh[n8 + g][tg * 2];
                const u16* krl = &skl[n8 + g][tg * 2];
                bh_[0] = *(const u32*)kr;        bh_[1] = *(const u32*)(kr + 8);
                bl_[0] = *(const u32*)krl;       bl_[1] = *(const u32*)(krl + 8);
                float cc[4] = {0.f, 0.f, 0.f, 0.f};
                mma16816(cc, a_hi, bh_);
                mma16816(cc, a_hi, bl_);
                mma16816(cc, a_lo, bh_);
                sc[hf][0] = cc[0]; sc[hf][1] = cc[1];
                sc[hf][2] = cc[2]; sc[hf][3] = cc[3];
            }
            u32 Ah[4], Al[4];
#pragma unroll
            for (int hf = 0; hf < 2; hf++) {
                int kb = t0 * BN + kc * 16 + hf * 8 + tg * 2;
                float p0 = __expf(sc[hf][0] + c0);
                float p1 = __expf(sc[hf][1] + c0);
                float p2 = __expf(sc[hf][2] + c1);
                float p3 = __expf(sc[hf][3] + c1);
                if (diag) {
                    if (kb     > qg0) p0 = 0.f;
                    if (kb + 1 > qg0) p1 = 0.f;
                    if (kb     > qg1) p2 = 0.f;
                    if (kb + 1 > qg1) p3 = 0.f;
                }
                den0 += p0 + p1;
                den1 += p2 + p3;
                float h0, l0, h1, l1, h2, l2, h3, l3;
                bsplit(p0, h0, l0); bsplit(p1, h1, l1);
                bsplit(p2, h2, l2); bsplit(p3, h3, l3);
                Ah[hf * 2]     = packbf2(h0, h1);
                Ah[hf * 2 + 1] = packbf2(h2, h3);
                Al[hf * 2]     = packbf2(l0, l1);
                Al[hf * 2 + 1] = packbf2(l2, l3);
            }
#pragma unroll
            for (int vt = 0; vt < 4; vt++) {
                u32 bvh[2], bvl[2];
                const u16* vr  = &svh[vt * 8 + g][kc * 16 + tg * 2];
                const u16* vrl = &svl[vt * 8 + g][kc * 16 + tg * 2];
                bvh[0] = *(const u32*)vr;   bvh[1] = *(const u32*)(vr + 8);
                bvl[0] = *(const u32*)vrl;  bvl[1] = *(const u32*)(vrl + 8);
                mma16816(num[vt], Ah, bvh);
                mma16816(num[vt], Ah, bvl);
                mma16816(num[vt], Al, bvh);
            }
        }
        __syncthreads();
    }

    den0 += __shfl_xor_sync(0xffffffffu, den0, 1);
    den0 += __shfl_xor_sync(0xffffffffu, den0, 2);
    den1 += __shfl_xor_sync(0xffffffffu, den1, 1);
    den1 += __shfl_xor_sync(0xffffffffu, den1, 2);
    const float inv0 = 1.f / den0, inv1 = 1.f / den1;

#pragma unroll
    for (int vt = 0; vt < 4; vt++) {
        int vd = vt * 8 + tg * 2;
        float a00 = e0[h * VB + vd],     b00 = e1[h * VB + vd];
        float a01 = e0[h * VB + vd + 1], b01 = e1[h * VB + vd + 1];
        float o00 = fmaf(b00 - a00, num[vt][0] * inv0, a00);
        float o01 = fmaf(b01 - a01, num[vt][1] * inv0, a01);
        float o10 = fmaf(b00 - a00, num[vt][2] * inv1, a00);
        float o11 = fmaf(b01 - a01, num[vt][3] * inv1, a01);
        // split and store as bf16 hi/lo for the O-projection GEMM
        float h0, l0, h1, l1;
        size_t i0 = ((size_t)(b * SS + qg0) * NH + h) * VB + vd;
        size_t i1 = ((size_t)(b * SS + qg1) * NH + h) * VB + vd;
        bsplit(o00, h0, l0); bsplit(o01, h1, l1);
        *(u32*)&ovhh[i0] = packbf2(h0, h1);
        *(u32*)&ovhl[i0] = packbf2(l0, l1);
        bsplit(o10, h0, l0); bsplit(o11, h1, l1);
        *(u32*)&ovhh[i1] = packbf2(h0, h1);
        *(u32*)&ovhl[i1] = packbf2(l0, l1);
    }
}

// ---------------------------------------------------------------------------
extern "C" void kernel_launch(void* const* d_in, const int* in_sizes, int n_in,
                              void* d_out, int out_size)
{
    const float* hs = (const float*)d_in[0];
    const float* Wq = (const float*)d_in[1];
    const float* Wk = (const float*)d_in[2];
    const float* Wv = (const float*)d_in[3];
    const float* Wo = (const float*)d_in[4];
    const float* e0 = (const float*)d_in[5];
    const float* e1 = (const float*)d_in[6];
    float* out = (float*)d_out;

    u16 *hsh, *hsl, *wth, *wtl, *woth, *wotl, *ovhh, *ovhl;
    u16 *qmh, *qml, *kh_, *kl_, *vth, *vtl;
    float *qkv, *qcp;
    cudaGetSymbolAddress((void**)&hsh,  g_hsh);
    cudaGetSymbolAddress((void**)&hsl,  g_hsl);
    cudaGetSymbolAddress((void**)&wth,  g_wth);
    cudaGetSymbolAddress((void**)&wtl,  g_wtl);
    cudaGetSymbolAddress((void**)&woth, g_woth);
    cudaGetSymbolAddress((void**)&wotl, g_wotl);
    cudaGetSymbolAddress((void**)&qkv,  g_qkv);
    cudaGetSymbolAddress((void**)&ovhh, g_ovhh);
    cudaGetSymbolAddress((void**)&ovhl, g_ovhl);
    cudaGetSymbolAddress((void**)&qcp,  g_qc);
    cudaGetSymbolAddress((void**)&qmh,  g_qmh);
    cudaGetSymbolAddress((void**)&qml,  g_qml);
    cudaGetSymbolAddress((void**)&kh_,  g_kh);
    cudaGetSymbolAddress((void**)&kl_,  g_kl);
    cudaGetSymbolAddress((void**)&vth,  g_vth);
    cudaGetSymbolAddress((void**)&vtl,  g_vtl);

    // Split hs; transpose+split weights (Wq/Wk/Wv concatenated in N)
    convert_split_kernel<<<(MROWS * DD / 8 + 255) / 256, 256>>>(hs, hsh, hsl, MROWS * DD);
    transpose_split_kernel<<<dim3(256 / 32, DD / 32), 256>>>(Wq, DD, 256, wth, wtl, DD, 0);
    transpose_split_kernel<<<dim3(64 / 32,  DD / 32), 256>>>(Wk, DD, 64,  wth, wtl, DD, 256);
    transpose_split_kernel<<<dim3(128 / 32, DD / 32), 256>>>(Wv, DD, 128, wth, wtl, DD, 320);
    transpose_split_kernel<<<dim3(DD / 32,  KO / 32), 256>>>(Wo, KO, DD,  woth, wotl, KO, 0);

    // Fused QKV projection (tensor cores, sigmoid epilogue)
    bgemm_kernel<1><<<dim3(NQKV / 64, MROWS / 128), 256>>>(
        hsh, hsl, wth, wtl, qkv, MROWS, NQKV, DD);

    // Operand conversions for attention
    convqk_kernel<true ><<<(MROWS * NH  + 127) / 128, 128>>>(qkv, NQKV, 0,   qmh, qml, qcp, NH);
    convqk_kernel<false><<<(MROWS * NKV + 127) / 128, 128>>>(qkv, NQKV, 256, kh_, kl_, nullptr, NKV);
    convv_kernel<<<dim3(SS / 64, NKV, BB), 256>>>(qkv, vth, vtl);

    // Tensor-core causal attention, emits split-bf16 ovh
    rosa_attn_mma<<<dim3(SS / QM, NH, BB), 256>>>(qmh, qml, qcp, kh_, kl_, vth, vtl,
                                                  e0, e1, ovhh, ovhl);

    // Output projection (tensor cores)
    bgemm_kernel<0><<<dim3(DD / 64, MROWS / 128), 256>>>(
        ovhh, ovhl, woth, wotl, out, MROWS, DD, KO);
}